// round 8
// baseline (speedup 1.0000x reference)
#include <cuda_runtime.h>
#include <math.h>

// ---------------- problem constants ----------------
#define DD     128          // feature dim
#define NCLS   32           // number of classes
#define OCHUNK 1024         // rows per hist/order chunk
#define GCHUNK 896          // rows per gemm CTA (multiple of BATCH)
#define MAXCHUNK 1024
#define GTPB   288          // gemm threads per block (9 warps)
#define BATCH  16           // rows staged per smem batch
#define MAXM   (1 << 19)

// ---------------- device scratch ----------------
__device__ float  g_cov[NCLS + 1][DD][DD];      // [32] = global (k_sumglobal)
__device__ int    g_chunk_cnt[MAXCHUNK][NCLS];
__device__ int    g_counts[NCLS];
__device__ int    g_class_start[NCLS + 1];
__device__ int    g_order[MAXM];
__device__ double g_logdet[NCLS + 1];

// ---------------- K1: per-chunk histogram + zero cov (proven) ----------------
__global__ void k_hist(const int* __restrict__ label, int M) {
    __shared__ int cnt[NCLS];
    int tid = threadIdx.x, b = blockIdx.x;
    if (tid < NCLS) cnt[tid] = 0;
    __syncthreads();
    int base = b * OCHUNK;
    int end  = min(base + OCHUNK, M);
    for (int r = base + tid; r < end; r += blockDim.x)
        atomicAdd(&cnt[label[r]], 1);
    __syncthreads();
    if (tid < NCLS) g_chunk_cnt[b][tid] = cnt[tid];

    float* cf = &g_cov[0][0][0];
    const int TOT = (NCLS + 1) * DD * DD;
    for (int i = b * blockDim.x + tid; i < TOT; i += gridDim.x * blockDim.x)
        cf[i] = 0.0f;
}

// ---------------- K2: offsets (serial-per-class, PROVEN in R4/R6) ----------------
// Note: loads are coalesced (warp reads one 128B line of g_chunk_cnt per iter)
// and address-independent, so they pipeline; this kernel is cheap and safe.
__global__ void k_scan(int nchunk) {
    int j = threadIdx.x;
    if (j < NCLS) {
        int tot = 0;
        for (int b = 0; b < nchunk; b++) tot += g_chunk_cnt[b][j];
        g_counts[j] = tot;
    }
    __syncthreads();
    if (j == 0) {
        int s = 0;
        for (int jj = 0; jj < NCLS; jj++) { g_class_start[jj] = s; s += g_counts[jj]; }
        g_class_start[NCLS] = s;
    }
    __syncthreads();
    if (j < NCLS) {
        int s = g_class_start[j];
        for (int b = 0; b < nchunk; b++) {
            int c = g_chunk_cnt[b][j];
            g_chunk_cnt[b][j] = s;
            s += c;
        }
    }
}

// ---------------- K3: stable class-sorted order (proven) ----------------
__global__ void k_order(const int* __restrict__ label, int M) {
    __shared__ int lbl[OCHUNK];
    int tid = threadIdx.x, b = blockIdx.x;
    int base = b * OCHUNK;
    int n = min(OCHUNK, M - base);
    for (int i = tid; i < n; i += blockDim.x) lbl[i] = label[base + i];
    __syncthreads();
    if (tid < NCLS) {
        int pos = g_chunk_cnt[b][tid];
        for (int r = 0; r < n; r++)
            if (lbl[r] == tid) g_order[pos++] = base + r;
    }
}

// ---------------- K4: segmented A^T A, f32x2, parity-split compute ----------------
typedef unsigned long long u64t;

__device__ __forceinline__ void accum_row2(const float* __restrict__ row,
                                           int ti, int tj, u64t acc[8][4]) {
    float4 a0 = *(const float4*)(row + (ti << 3));
    float4 a1 = *(const float4*)(row + (ti << 3) + 4);
    // b operand loaded directly as packed f32x2 pairs (lo = even col, hi = odd col)
    ulonglong2 bq0 = *(const ulonglong2*)(row + (tj << 3));
    ulonglong2 bq1 = *(const ulonglong2*)(row + (tj << 3) + 4);
    u64t bp[4] = {bq0.x, bq0.y, bq1.x, bq1.y};
    float av[8] = {a0.x, a0.y, a0.z, a0.w, a1.x, a1.y, a1.z, a1.w};
#pragma unroll
    for (int a = 0; a < 8; a++) {
        u64t ad;
        asm("mov.b64 %0, {%1, %1};" : "=l"(ad) : "f"(av[a]));
#pragma unroll
        for (int b = 0; b < 4; b++)
            asm("fma.rn.f32x2 %0, %1, %2, %0;" : "+l"(acc[a][b]) : "l"(ad), "l"(bp[b]));
    }
}

__device__ __forceinline__ void flush_acc2(int cls, int ti, int tj, u64t acc[8][4]) {
#pragma unroll
    for (int a = 0; a < 8; a++)
#pragma unroll
        for (int b = 0; b < 4; b++) {
            float lo, hi;
            asm("mov.b64 {%0, %1}, %2;" : "=f"(lo), "=f"(hi) : "l"(acc[a][b]));
            int r = ti * 8 + a, c = tj * 8 + 2 * b;
            atomicAdd(&g_cov[cls][r][c],     lo);
            atomicAdd(&g_cov[cls][r][c + 1], hi);
            acc[a][b] = 0ull;
        }
}

__global__ void __launch_bounds__(GTPB, 2) k_gemm(const float* __restrict__ Z, int M) {
    __shared__ float s_rows[BATCH][DD];   // 8 KB
    int tid = threadIdx.x;
    int wid = tid >> 5, lane = tid & 31;
    int p0 = blockIdx.x * GCHUNK;
    if (p0 >= M) return;
    int pend = min(p0 + GCHUNK, M);

    // compute mapping: two parity groups of 136 threads, each owns full triangle
    int grp = (tid >= 144) ? 1 : 0;
    int id  = tid - grp * 144;
    int ti = -1, tj = -1;
    if (id < 136) {
        int i = 0, rem = id;
        while (rem >= 16 - i) { rem -= 16 - i; i++; }
        ti = i; tj = i + rem;
    }

    u64t acc[8][4];
#pragma unroll
    for (int a = 0; a < 8; a++)
#pragma unroll
        for (int b = 0; b < 4; b++) acc[a][b] = 0ull;

    // class of first position (clamped: cur can never leave [0, NCLS-1])
    int cur = 0;
    while (cur < NCLS - 1 && g_class_start[cur + 1] <= p0) cur++;
    int nextb = g_class_start[cur + 1];

    // staging role: warps 0-7, warp w stages rows 2w, 2w+1 (half-warp each)
    int srow = 2 * wid + (lane >> 4);
    int scol = lane & 15;

    for (int p = p0; p < pend; p += BATCH) {
        int nb = min(BATCH, pend - p);
        __syncthreads();                       // previous batch fully consumed
        if (wid < 8) {
            int pos = p + srow;
            if (pos < pend) {
                int row = g_order[pos];        // half-warp broadcast
                const float4* src = (const float4*)(Z + (size_t)row * DD);
                float4* dst = (float4*)s_rows[srow];
                dst[scol]      = src[scol];
                dst[scol + 16] = src[scol + 16];
            }
        }
        __syncthreads();

        if (nb == BATCH && p + BATCH <= nextb) {
            if (ti >= 0) {
#pragma unroll
                for (int k = 0; k < BATCH; k += 2)
                    accum_row2(s_rows[k + grp], ti, tj, acc);
            }
        } else {
            for (int k = 0; k < nb; k++) {
                if (p + k >= nextb && cur < NCLS - 1) {
                    if (ti >= 0) flush_acc2(cur, ti, tj, acc);
                    cur++;
                    while (cur < NCLS - 1 && g_class_start[cur + 1] <= p + k) cur++;
                    nextb = g_class_start[cur + 1];
                }
                if (ti >= 0 && (k & 1) == grp)
                    accum_row2(s_rows[k], ti, tj, acc);
            }
        }
    }
    if (ti >= 0) flush_acc2(cur, ti, tj, acc);
}

// ---------------- K4b: global cov = sum of class covs ----------------
__global__ void k_sumglobal(void) {
    int r = blockIdx.x, c = threadIdx.x;
    float s = 0.0f;
#pragma unroll
    for (int j = 0; j < NCLS; j++) s += g_cov[j][r][c];
    g_cov[NCLS][r][c] = s;
}

// ------- K5: fp32 Cholesky with fp64-compensated diagonal (proven) -------
__global__ void k_cholesky(void) {
    extern __shared__ float sA[];
    __shared__ float  s_col[DD];
    __shared__ double s_pivot;
    __shared__ double s_logs[DD];
    const int LDA = DD + 1;
    int j = blockIdx.x;
    int tid = threadIdx.x;

    if (j < NCLS && g_counts[j] == 0) {
        if (tid == 0) g_logdet[j] = 0.0;
        return;
    }
    const float (*C)[DD] = g_cov[j];
    for (int c = 0; c < DD; c++) {
        int lo = min(tid, c), hi = max(tid, c);
        sA[tid * LDA + c] = C[lo][hi];
    }
    double mydiag = (double)C[tid][tid];
    __syncthreads();

    for (int k = 0; k < DD; k++) {
        if (tid == k) { s_pivot = mydiag; s_logs[k] = log(mydiag); }
        __syncthreads();
        float inv = rsqrtf((float)s_pivot);
        float lrk = 0.0f;
        if (tid > k) {
            lrk = sA[tid * LDA + k] * inv;
            s_col[tid] = lrk;
            mydiag -= (double)lrk * (double)lrk;
        }
        __syncthreads();
        if (tid > k) {
            float* rowp = &sA[tid * LDA];
            int c = k + 1;
            for (; c + 3 < tid; c += 4) {
                rowp[c + 0] -= lrk * s_col[c + 0];
                rowp[c + 1] -= lrk * s_col[c + 1];
                rowp[c + 2] -= lrk * s_col[c + 2];
                rowp[c + 3] -= lrk * s_col[c + 3];
            }
            for (; c < tid; c++) rowp[c] -= lrk * s_col[c];
        }
        __syncthreads();
    }
    __shared__ double s_red[DD];
    s_red[tid] = s_logs[tid];
    __syncthreads();
    for (int s = DD / 2; s > 0; s >>= 1) {
        if (tid < s) s_red[tid] += s_red[tid + s];
        __syncthreads();
    }
    if (tid == 0) g_logdet[j] = s_red[0];
}

// ---------------- K6: combine (one warp, proven) ----------------
__global__ void k_finalize(float* out, int M) {
    int lane = threadIdx.x;
    double m = (double)M;
    double term = 0.0;
    if (lane < NCLS) {
        int mj = g_counts[lane];
        if (mj > 0) {
            double cj = (double)DD / ((double)mj * 0.01);
            term = ((double)DD * log(cj) + g_logdet[lane]) * (double)mj / (2.0 * m);
        }
    }
#pragma unroll
    for (int d = 16; d > 0; d >>= 1)
        term += __shfl_down_sync(0xFFFFFFFFu, term, d);
    if (lane == 0) {
        double c = (double)DD / (m * 0.01);
        double expd = ((double)DD * log(c) + g_logdet[NCLS]) * 0.5;
        out[0] = (float)(term - expd);
    }
}

// ---------------- launch ----------------
extern "C" void kernel_launch(void* const* d_in, const int* in_sizes, int n_in,
                              void* d_out, int out_size) {
    const float* Z     = (const float*)d_in[0];
    const int*   label = (const int*)d_in[1];
    int M = in_sizes[1];
    int nchunk = (M + OCHUNK - 1) / OCHUNK;
    int ggrid  = (M + GCHUNK - 1) / GCHUNK;

    cudaFuncSetAttribute(k_cholesky, cudaFuncAttributeMaxDynamicSharedMemorySize,
                         DD * (DD + 1) * (int)sizeof(float));

    k_hist<<<nchunk, 256>>>(label, M);
    k_scan<<<1, 32>>>(nchunk);
    k_order<<<nchunk, 256>>>(label, M);
    k_gemm<<<ggrid, GTPB>>>(Z, M);
    k_sumglobal<<<DD, DD>>>();
    k_cholesky<<<NCLS + 1, DD, DD * (DD + 1) * (int)sizeof(float)>>>();
    k_finalize<<<1, 32>>>((float*)d_out, M);
}

// round 9
// speedup vs baseline: 1.0146x; 1.0146x over previous
#include <cuda_runtime.h>
#include <math.h>

// ---------------- problem constants ----------------
#define DD     128          // feature dim
#define NCLS   32           // number of classes
#define OCHUNK 1024         // rows per hist/order chunk
#define GCHUNK 896          // rows per gemm CTA (multiple of BATCH)
#define MAXCHUNK 1024
#define GTPB   288          // gemm threads per block (9 warps)
#define BATCH  16           // rows staged per smem batch
#define MAXM   (1 << 19)
#define SCAN_GROUPS 16      // supports nchunk <= 512 (= MAXM/OCHUNK)

// ---------------- device scratch ----------------
__device__ float  g_cov[NCLS + 1][DD][DD];      // [32] = global (k_sumglobal)
__device__ int    g_chunk_cnt[MAXCHUNK][NCLS];
__device__ int    g_counts[NCLS];
__device__ int    g_class_start[NCLS + 1];
__device__ int    g_order[MAXM];
__device__ double g_logdet[NCLS + 1];

// ---------------- K1: per-chunk histogram + zero cov (proven) ----------------
__global__ void k_hist(const int* __restrict__ label, int M) {
    __shared__ int cnt[NCLS];
    int tid = threadIdx.x, b = blockIdx.x;
    if (tid < NCLS) cnt[tid] = 0;
    __syncthreads();
    int base = b * OCHUNK;
    int end  = min(base + OCHUNK, M);
    for (int r = base + tid; r < end; r += blockDim.x)
        atomicAdd(&cnt[label[r]], 1);
    __syncthreads();
    if (tid < NCLS) g_chunk_cnt[b][tid] = cnt[tid];

    float* cf = &g_cov[0][0][0];
    const int TOT = (NCLS + 1) * DD * DD;
    for (int i = b * blockDim.x + tid; i < TOT; i += gridDim.x * blockDim.x)
        cf[i] = 0.0f;
}

// ------- K2: parallel offsets. Warp j = class j; lane l scans chunks 32*i+l.
// Prefix order equals chunk order by construction (group i ascending, lanes
// ascending within group), so g_class_start is monotone and bases are exact.
__global__ void k_scan(int nchunk) {
    __shared__ int s_tot[NCLS];
    __shared__ int s_start[NCLS + 1];
    int j = threadIdx.x >> 5;
    int l = threadIdx.x & 31;

    int c[SCAN_GROUPS], excl[SCAN_GROUPS];
    int run = 0;
#pragma unroll
    for (int i = 0; i < SCAN_GROUPS; i++) {
        int b = 32 * i + l;
        c[i] = (b < nchunk) ? g_chunk_cnt[b][j] : 0;
        int incl = c[i];
#pragma unroll
        for (int d = 1; d < 32; d <<= 1) {
            int v = __shfl_up_sync(0xFFFFFFFFu, incl, d);
            if (l >= d) incl += v;
        }
        excl[i] = run + (incl - c[i]);                    // chunks before b
        run += __shfl_sync(0xFFFFFFFFu, incl, 31);        // group total
    }
    if (l == 0) s_tot[j] = run;
    __syncthreads();
    if (threadIdx.x == 0) {
        int s = 0;
        for (int jj = 0; jj < NCLS; jj++) { s_start[jj] = s; s += s_tot[jj]; }
        s_start[NCLS] = s;
    }
    __syncthreads();
    if (l == 0) {
        g_counts[j] = s_tot[j];
        g_class_start[j] = s_start[j];
        if (j == 0) g_class_start[NCLS] = s_start[NCLS];
    }
    int base = s_start[j];
#pragma unroll
    for (int i = 0; i < SCAN_GROUPS; i++) {
        int b = 32 * i + l;
        if (b < nchunk) g_chunk_cnt[b][j] = base + excl[i];
    }
}

// ---------------- K3: stable class-sorted order (proven + write guard) ------
__global__ void k_order(const int* __restrict__ label, int M) {
    __shared__ int lbl[OCHUNK];
    int tid = threadIdx.x, b = blockIdx.x;
    int base = b * OCHUNK;
    int n = min(OCHUNK, M - base);
    for (int i = tid; i < n; i += blockDim.x) lbl[i] = label[base + i];
    __syncthreads();
    if (tid < NCLS) {
        int pos = g_chunk_cnt[b][tid];
        for (int r = 0; r < n; r++)
            if (lbl[r] == tid) {
                if (pos >= 0 && pos < MAXM) g_order[pos] = base + r;
                pos++;
            }
    }
}

// ---------------- K4: segmented A^T A, f32x2, parity split, double-buffered --
typedef unsigned long long u64t;

__device__ __forceinline__ void accum_row2(const float* __restrict__ row,
                                           int ti, int tj, u64t acc[8][4]) {
    float4 a0 = *(const float4*)(row + (ti << 3));
    float4 a1 = *(const float4*)(row + (ti << 3) + 4);
    ulonglong2 bq0 = *(const ulonglong2*)(row + (tj << 3));
    ulonglong2 bq1 = *(const ulonglong2*)(row + (tj << 3) + 4);
    u64t bp[4] = {bq0.x, bq0.y, bq1.x, bq1.y};
    float av[8] = {a0.x, a0.y, a0.z, a0.w, a1.x, a1.y, a1.z, a1.w};
#pragma unroll
    for (int a = 0; a < 8; a++) {
        u64t ad;
        asm("mov.b64 %0, {%1, %1};" : "=l"(ad) : "f"(av[a]));
#pragma unroll
        for (int b = 0; b < 4; b++)
            asm("fma.rn.f32x2 %0, %1, %2, %0;" : "+l"(acc[a][b]) : "l"(ad), "l"(bp[b]));
    }
}

__device__ __forceinline__ void flush_acc2(int cls, int ti, int tj, u64t acc[8][4]) {
#pragma unroll
    for (int a = 0; a < 8; a++)
#pragma unroll
        for (int b = 0; b < 4; b++) {
            float lo, hi;
            asm("mov.b64 {%0, %1}, %2;" : "=f"(lo), "=f"(hi) : "l"(acc[a][b]));
            int r = ti * 8 + a, c = tj * 8 + 2 * b;
            atomicAdd(&g_cov[cls][r][c],     lo);
            atomicAdd(&g_cov[cls][r][c + 1], hi);
            acc[a][b] = 0ull;
        }
}

__global__ void __launch_bounds__(GTPB, 2) k_gemm(const float* __restrict__ Z, int M) {
    __shared__ float s_rows[2][BATCH][DD];   // 16 KB, double buffered
    int tid = threadIdx.x;
    int wid = tid >> 5, lane = tid & 31;
    int p0 = blockIdx.x * GCHUNK;
    if (p0 >= M) return;
    int pend = min(p0 + GCHUNK, M);

    // compute mapping: two parity groups of 136 threads, each owns full triangle
    int grp = (tid >= 144) ? 1 : 0;
    int id  = tid - grp * 144;
    int ti = -1, tj = -1;
    if (id < 136) {
        int i = 0, rem = id;
        while (rem >= 16 - i) { rem -= 16 - i; i++; }
        ti = i; tj = i + rem;
    }

    u64t acc[8][4];
#pragma unroll
    for (int a = 0; a < 8; a++)
#pragma unroll
        for (int b = 0; b < 4; b++) acc[a][b] = 0ull;

    int cur = 0;
    while (cur < NCLS - 1 && g_class_start[cur + 1] <= p0) cur++;
    int nextb = g_class_start[cur + 1];

    // staging role: warps 0-7, warp w stages rows 2w, 2w+1 (half-warp each)
    int srow = 2 * wid + (lane >> 4);
    int scol = lane & 15;

    // prologue: stage batch 0 into buffer 0
    if (wid < 8) {
        int pos = p0 + srow;
        if (pos < pend) {
            int row = g_order[pos];
            const float4* src = (const float4*)(Z + (size_t)row * DD);
            float4* dst = (float4*)s_rows[0][srow];
            dst[scol]      = src[scol];
            dst[scol + 16] = src[scol + 16];
        }
    }
    __syncthreads();

    int ib = 0;
    for (int p = p0; p < pend; p += BATCH, ib ^= 1) {
        int nb = min(BATCH, pend - p);
        // prefetch next batch into the other buffer (overlaps compute below)
        if (wid < 8 && p + BATCH < pend) {
            int pos = p + BATCH + srow;
            if (pos < pend) {
                int row = g_order[pos];
                const float4* src = (const float4*)(Z + (size_t)row * DD);
                float4* dst = (float4*)s_rows[ib ^ 1][srow];
                dst[scol]      = src[scol];
                dst[scol + 16] = src[scol + 16];
            }
        }

        if (nb == BATCH && p + BATCH <= nextb) {
            if (ti >= 0) {
#pragma unroll
                for (int k = 0; k < BATCH; k += 2)
                    accum_row2(s_rows[ib][k + grp], ti, tj, acc);
            }
        } else {
            for (int k = 0; k < nb; k++) {
                if (p + k >= nextb && cur < NCLS - 1) {
                    if (ti >= 0) flush_acc2(cur, ti, tj, acc);
                    cur++;
                    while (cur < NCLS - 1 && g_class_start[cur + 1] <= p + k) cur++;
                    nextb = g_class_start[cur + 1];
                }
                if (ti >= 0 && (k & 1) == grp)
                    accum_row2(s_rows[ib][k], ti, tj, acc);
            }
        }
        __syncthreads();   // next batch staged AND this buffer consumed
    }
    if (ti >= 0) flush_acc2(cur, ti, tj, acc);
}

// ---------------- K4b: global cov = sum of class covs ----------------
__global__ void k_sumglobal(void) {
    int r = blockIdx.x, c = threadIdx.x;
    float s = 0.0f;
#pragma unroll
    for (int j = 0; j < NCLS; j++) s += g_cov[j][r][c];
    g_cov[NCLS][r][c] = s;
}

// ------- K5: fp32 Cholesky, fp64-compensated diagonal, logs hoisted ---------
__global__ void k_cholesky(void) {
    extern __shared__ float sA[];
    __shared__ float  s_col[DD];
    __shared__ double s_pivot;
    __shared__ double s_diag[DD];
    const int LDA = DD + 1;
    int j = blockIdx.x;
    int tid = threadIdx.x;

    if (j < NCLS && g_counts[j] == 0) {
        if (tid == 0) g_logdet[j] = 0.0;
        return;
    }
    const float (*C)[DD] = g_cov[j];
    for (int c = 0; c < DD; c++) {
        int lo = min(tid, c), hi = max(tid, c);
        sA[tid * LDA + c] = C[lo][hi];
    }
    double mydiag = (double)C[tid][tid];
    __syncthreads();

    for (int k = 0; k < DD; k++) {
        if (tid == k) { s_pivot = mydiag; s_diag[k] = mydiag; }  // log deferred
        __syncthreads();
        float inv = rsqrtf((float)s_pivot);
        float lrk = 0.0f;
        if (tid > k) {
            lrk = sA[tid * LDA + k] * inv;
            s_col[tid] = lrk;
            mydiag -= (double)lrk * (double)lrk;
        }
        __syncthreads();
        if (tid > k) {
            float* rowp = &sA[tid * LDA];
            int c = k + 1;
            for (; c + 3 < tid; c += 4) {
                rowp[c + 0] -= lrk * s_col[c + 0];
                rowp[c + 1] -= lrk * s_col[c + 1];
                rowp[c + 2] -= lrk * s_col[c + 2];
                rowp[c + 3] -= lrk * s_col[c + 3];
            }
            for (; c < tid; c++) rowp[c] -= lrk * s_col[c];
        }
        __syncthreads();
    }
    // parallel logs (128 at once, instead of 128 serial on the critical path)
    __shared__ double s_red[DD];
    s_red[tid] = log(s_diag[tid]);
    __syncthreads();
    for (int s = DD / 2; s > 0; s >>= 1) {
        if (tid < s) s_red[tid] += s_red[tid + s];
        __syncthreads();
    }
    if (tid == 0) g_logdet[j] = s_red[0];
}

// ---------------- K6: combine (one warp, proven) ----------------
__global__ void k_finalize(float* out, int M) {
    int lane = threadIdx.x;
    double m = (double)M;
    double term = 0.0;
    if (lane < NCLS) {
        int mj = g_counts[lane];
        if (mj > 0) {
            double cj = (double)DD / ((double)mj * 0.01);
            term = ((double)DD * log(cj) + g_logdet[lane]) * (double)mj / (2.0 * m);
        }
    }
#pragma unroll
    for (int d = 16; d > 0; d >>= 1)
        term += __shfl_down_sync(0xFFFFFFFFu, term, d);
    if (lane == 0) {
        double c = (double)DD / (m * 0.01);
        double expd = ((double)DD * log(c) + g_logdet[NCLS]) * 0.5;
        out[0] = (float)(term - expd);
    }
}

// ---------------- launch ----------------
extern "C" void kernel_launch(void* const* d_in, const int* in_sizes, int n_in,
                              void* d_out, int out_size) {
    const float* Z     = (const float*)d_in[0];
    const int*   label = (const int*)d_in[1];
    int M = in_sizes[1];
    int nchunk = (M + OCHUNK - 1) / OCHUNK;
    int ggrid  = (M + GCHUNK - 1) / GCHUNK;

    cudaFuncSetAttribute(k_cholesky, cudaFuncAttributeMaxDynamicSharedMemorySize,
                         DD * (DD + 1) * (int)sizeof(float));

    k_hist<<<nchunk, 256>>>(label, M);
    k_scan<<<1, 1024>>>(nchunk);
    k_order<<<nchunk, 256>>>(label, M);
    k_gemm<<<ggrid, GTPB>>>(Z, M);
    k_sumglobal<<<DD, DD>>>();
    k_cholesky<<<NCLS + 1, DD, DD * (DD + 1) * (int)sizeof(float)>>>();
    k_finalize<<<1, 32>>>((float*)d_out, M);
}